// round 4
// baseline (speedup 1.0000x reference)
#include <cuda_runtime.h>

#define NN 100000
#define EE 3200000
#define FIN 512
#define HID 16
#define CC 40

// ---------------- scratch (static device globals; no runtime alloc) ----------
__device__ float  g_deg[NN];
__device__ float  g_dis[NN];
__device__ float  g_norm[EE];
__device__ float4 g_h1[NN * 4];    // h1 = x@W1, [N,16] viewed as [N,4] float4
__device__ float4 g_agg1[NN * 4];  // layer-1 aggregation
__device__ float4 g_agg2[NN * 4];  // layer-2 aggregation (16-dim, pre-W2)

// ---------------- zero init ---------------------------------------------------
__global__ void zero_kernel() {
    int i = blockIdx.x * blockDim.x + threadIdx.x;
    float4 z = make_float4(0.f, 0.f, 0.f, 0.f);
    if (i < NN) g_deg[i] = 0.f;
    if (i < NN * 4) { g_agg1[i] = z; g_agg2[i] = z; }
}

// ---------------- degree ------------------------------------------------------
__global__ void deg_kernel(const int* __restrict__ ei,
                           const float* __restrict__ w) {
    int e = blockIdx.x * blockDim.x + threadIdx.x;
    if (e >= EE) return;
    atomicAdd(&g_deg[ei[EE + e]], w[e]);
}

__global__ void dis_kernel() {
    int n = blockIdx.x * blockDim.x + threadIdx.x;
    if (n >= NN) return;
    float d = g_deg[n];
    g_dis[n] = (d > 0.f) ? rsqrtf(d) : 0.f;
}

__global__ void norm_kernel(const int* __restrict__ ei,
                            const float* __restrict__ w) {
    int e = blockIdx.x * blockDim.x + threadIdx.x;
    if (e >= EE) return;
    g_norm[e] = g_dis[ei[e]] * w[e] * g_dis[ei[EE + e]];
}

// ---------------- GEMM1: h1 = x @ W1  (100000x512 @ 512x16) ------------------
// Block: 128 threads, tile 128 nodes x 16 f. Thread tile: 8 nodes x 2 f.
// x tile stored transposed in smem with XOR swizzle -> conflict-free stores
// (scalar) and conflict-free float4 reads in the mainloop.
__global__ void __launch_bounds__(128) gemm1_kernel(const float* __restrict__ x,
                                                    const float* __restrict__ W1) {
    __shared__ float4 xs4[32][33];   // [k within chunk][swizzled node-f4], pad 33
    __shared__ float  ws[512];       // W chunk [32 k][16 f]
    int tid = threadIdx.x;
    int fg = tid >> 4;               // 0..7  -> f = 2*fg, 2*fg+1
    int ng = tid & 15;               // 0..15 -> nodes ng*8 .. ng*8+7
    int nodeBase = blockIdx.x * 128;

    float acc[8][2];
#pragma unroll
    for (int i = 0; i < 8; ++i) { acc[i][0] = 0.f; acc[i][1] = 0.f; }

    for (int kc = 0; kc < FIN / 32; ++kc) {
        __syncthreads();
        // W chunk: 512 floats, one float4 per thread, coalesced
        ((float4*)ws)[tid] = ((const float4*)(W1 + kc * 512))[tid];
        // x chunk: 128 nodes x 32 k, transposed + swizzled into smem
#pragma unroll
        for (int v = 0; v < 8; ++v) {
            int j = v * 128 + tid;
            int nl = j >> 3;                  // local node 0..127
            int kq = j & 7;                   // float4 index along k, 0..7
            int node = nodeBase + nl;
            if (node >= NN) node = NN - 1;    // safe clamp (store-guarded later)
            float4 xv = *(const float4*)(x + (size_t)node * FIN + kc * 32 + kq * 4);
            int pcol = (((nl >> 2) ^ kq) << 2) + (nl & 3);   // swizzled column (floats)
            float* base = (float*)&xs4[0][0] + (kq * 4) * 132 + pcol;
            base[0]       = xv.x;
            base[132]     = xv.y;
            base[264]     = xv.z;
            base[396]     = xv.w;
        }
        __syncthreads();
#pragma unroll
        for (int k = 0; k < 32; ++k) {
            float2 wv = *(const float2*)&ws[k * 16 + fg * 2];
            int p  = k >> 2;
            int u0 = (2 * ng) ^ p;            // phys f4 col of logical (2*ng)
            float4 a0 = xs4[k][u0];           // nodes ng*8 .. +3
            float4 a1 = xs4[k][u0 ^ 1];       // nodes ng*8+4 .. +7
            acc[0][0] += a0.x * wv.x; acc[0][1] += a0.x * wv.y;
            acc[1][0] += a0.y * wv.x; acc[1][1] += a0.y * wv.y;
            acc[2][0] += a0.z * wv.x; acc[2][1] += a0.z * wv.y;
            acc[3][0] += a0.w * wv.x; acc[3][1] += a0.w * wv.y;
            acc[4][0] += a1.x * wv.x; acc[4][1] += a1.x * wv.y;
            acc[5][0] += a1.y * wv.x; acc[5][1] += a1.y * wv.y;
            acc[6][0] += a1.z * wv.x; acc[6][1] += a1.z * wv.y;
            acc[7][0] += a1.w * wv.x; acc[7][1] += a1.w * wv.y;
        }
    }
    float* h1 = (float*)g_h1;
#pragma unroll
    for (int i = 0; i < 8; ++i) {
        int node = nodeBase + ng * 8 + i;
        if (node < NN) {
            h1[node * 16 + fg * 2 + 0] = acc[i][0];
            h1[node * 16 + fg * 2 + 1] = acc[i][1];
        }
    }
}

// ---------------- propagation: 4 threads per edge, scalar atomics ------------
__global__ void prop1_kernel(const int* __restrict__ ei) {
    int t = blockIdx.x * blockDim.x + threadIdx.x;
    int e = t >> 2;
    if (e >= EE) return;
    int q = t & 3;
    int r = ei[e];
    int c = ei[EE + e];
    float nw = g_norm[e];
    float4 v = g_h1[r * 4 + q];
    float* dst = (float*)&g_agg1[c * 4 + q];
    atomicAdd(dst + 0, nw * v.x);
    atomicAdd(dst + 1, nw * v.y);
    atomicAdd(dst + 2, nw * v.z);
    atomicAdd(dst + 3, nw * v.w);
}

// layer-2 propagate with fused relu(agg1 + b1) at gather time
__global__ void prop2_kernel(const int* __restrict__ ei,
                             const float* __restrict__ b1) {
    int t = blockIdx.x * blockDim.x + threadIdx.x;
    int e = t >> 2;
    if (e >= EE) return;
    int q = t & 3;
    int r = ei[e];
    int c = ei[EE + e];
    float nw = g_norm[e];
    float4 b = ((const float4*)b1)[q];
    float4 v = g_agg1[r * 4 + q];
    float* dst = (float*)&g_agg2[c * 4 + q];
    atomicAdd(dst + 0, fmaxf(v.x + b.x, 0.f) * nw);
    atomicAdd(dst + 1, fmaxf(v.y + b.y, 0.f) * nw);
    atomicAdd(dst + 2, fmaxf(v.z + b.z, 0.f) * nw);
    atomicAdd(dst + 3, fmaxf(v.w + b.w, 0.f) * nw);
}

// ---------------- epilogue: out = log_softmax(agg2 @ W2 + b2) -----------------
__global__ void __launch_bounds__(256) out_kernel(const float* __restrict__ W2,
                                                  const float* __restrict__ b2,
                                                  float* __restrict__ out) {
    __shared__ float w2s[HID * CC];
    __shared__ float b2s[CC];
    int tid = threadIdx.x;
    for (int i = tid; i < HID * CC; i += 256) w2s[i] = W2[i];
    if (tid < CC) b2s[tid] = b2[tid];
    __syncthreads();

    int n = blockIdx.x * blockDim.x + tid;
    if (n >= NN) return;

    float a[16];
    float4* ap = (float4*)a;
    ap[0] = g_agg2[n * 4 + 0];
    ap[1] = g_agg2[n * 4 + 1];
    ap[2] = g_agg2[n * 4 + 2];
    ap[3] = g_agg2[n * 4 + 3];

    float logit[CC];
    float mx = -1e30f;
#pragma unroll
    for (int j = 0; j < CC; ++j) {
        float s = b2s[j];
#pragma unroll
        for (int i = 0; i < 16; ++i) s += a[i] * w2s[i * CC + j];
        logit[j] = s;
        mx = fmaxf(mx, s);
    }
    float sum = 0.f;
#pragma unroll
    for (int j = 0; j < CC; ++j) sum += expf(logit[j] - mx);
    float lse = mx + logf(sum);
#pragma unroll
    for (int j = 0; j < CC; ++j) out[(size_t)n * CC + j] = logit[j] - lse;
}

// ---------------- launch ------------------------------------------------------
extern "C" void kernel_launch(void* const* d_in, const int* in_sizes, int n_in,
                              void* d_out, int out_size) {
    const float* x  = (const float*)d_in[0];
    const int*   ei = (const int*)d_in[1];     // int32 (harness converts int64)
    const float* w  = (const float*)d_in[2];
    const float* W1 = (const float*)d_in[3];
    const float* b1 = (const float*)d_in[4];
    const float* W2 = (const float*)d_in[5];
    const float* b2 = (const float*)d_in[6];
    float*       out = (float*)d_out;

    zero_kernel<<<(NN * 4 + 255) / 256, 256>>>();
    deg_kernel<<<(EE + 255) / 256, 256>>>(ei, w);
    dis_kernel<<<(NN + 255) / 256, 256>>>();
    norm_kernel<<<(EE + 255) / 256, 256>>>(ei, w);
    gemm1_kernel<<<(NN + 127) / 128, 128>>>(x, W1);
    prop1_kernel<<<(EE * 4 + 255) / 256, 256>>>(ei);
    prop2_kernel<<<(EE * 4 + 255) / 256, 256>>>(ei, b1);
    out_kernel<<<(NN + 255) / 256, 256>>>(W2, b2, out);
}

// round 6
// speedup vs baseline: 1.3324x; 1.3324x over previous
#include <cuda_runtime.h>

#define NN 100000
#define EE 3200000
#define FIN 512
#define HID 16
#define CC 40
#define NB 391          // ceil(NN/256) scan blocks

// ---------------- scratch (static device globals) -----------------------------
__device__ float  g_deg[NN];
__device__ float  g_dis[NN];
__device__ int    g_cnt[NN];
__device__ int    g_cur[NN];
__device__ int    g_base[NN + 1];
__device__ int    g_bsum[NB];
__device__ int    g_bsumx[NB];
__device__ int2   g_edge[EE];      // dest-sorted (src, norm-as-int)
__device__ float4 g_h1[NN * 4];    // h1 = x@W1, [N,16] as [N,4] float4
__device__ float4 g_agg1[NN * 4];  // layer-1 aggregation
__device__ float4 g_agg2[NN * 4];  // layer-2 aggregation (16-dim, pre-W2)

// ---------------- zero init ---------------------------------------------------
__global__ void zero_kernel() {
    int i = blockIdx.x * blockDim.x + threadIdx.x;
    if (i < NN) { g_deg[i] = 0.f; g_cnt[i] = 0; g_cur[i] = 0; }
}

// ---------------- degree (weighted) + in-degree count -------------------------
__global__ void deg_kernel(const int* __restrict__ ei,
                           const float* __restrict__ w) {
    int e = blockIdx.x * blockDim.x + threadIdx.x;
    if (e >= EE) return;
    int c = ei[EE + e];
    atomicAdd(&g_deg[c], w[e]);
    atomicAdd(&g_cnt[c], 1);
}

__global__ void dis_kernel() {
    int n = blockIdx.x * blockDim.x + threadIdx.x;
    if (n >= NN) return;
    float d = g_deg[n];
    g_dis[n] = (d > 0.f) ? rsqrtf(d) : 0.f;
}

// ---------------- 3-kernel exclusive scan of g_cnt -> g_base ------------------
__global__ void scanA_kernel() {
    __shared__ int s[256];
    int tid = threadIdx.x;
    int i = blockIdx.x * 256 + tid;
    int v = (i < NN) ? g_cnt[i] : 0;
    s[tid] = v;
    __syncthreads();
    for (int off = 1; off < 256; off <<= 1) {
        int t = (tid >= off) ? s[tid - off] : 0;
        __syncthreads();
        s[tid] += t;
        __syncthreads();
    }
    if (i < NN) g_base[i] = s[tid] - v;          // exclusive, intra-block
    if (tid == 255) g_bsum[blockIdx.x] = s[255];
}

__global__ void scanB_kernel() {
    __shared__ int s[512];
    int tid = threadIdx.x;
    int v = (tid < NB) ? g_bsum[tid] : 0;
    s[tid] = v;
    __syncthreads();
    for (int off = 1; off < 512; off <<= 1) {
        int t = (tid >= off) ? s[tid - off] : 0;
        __syncthreads();
        s[tid] += t;
        __syncthreads();
    }
    if (tid < NB) g_bsumx[tid] = s[tid] - v;     // exclusive block offsets
}

__global__ void scanC_kernel() {
    int i = blockIdx.x * blockDim.x + threadIdx.x;
    if (i < NN) g_base[i] += g_bsumx[i >> 8];
    if (i == 0) g_base[NN] = EE;
}

// ---------------- scatter edges into dest-sorted CSR (norm fused) -------------
__global__ void scatter_kernel(const int* __restrict__ ei,
                               const float* __restrict__ w) {
    int e = blockIdx.x * blockDim.x + threadIdx.x;
    if (e >= EE) return;
    int r = ei[e];
    int c = ei[EE + e];
    float nw = g_dis[r] * w[e] * g_dis[c];
    int pos = g_base[c] + atomicAdd(&g_cur[c], 1);
    g_edge[pos] = make_int2(r, __float_as_int(nw));
}

// ---------------- GEMM1: h1 = x @ W1  (100000x512 @ 512x16) ------------------
__global__ void __launch_bounds__(128) gemm1_kernel(const float* __restrict__ x,
                                                    const float* __restrict__ W1) {
    __shared__ float4 xs4[32][33];
    __shared__ float  ws[512];
    int tid = threadIdx.x;
    int fg = tid >> 4;
    int ng = tid & 15;
    int nodeBase = blockIdx.x * 128;

    float acc[8][2];
#pragma unroll
    for (int i = 0; i < 8; ++i) { acc[i][0] = 0.f; acc[i][1] = 0.f; }

    for (int kc = 0; kc < FIN / 32; ++kc) {
        __syncthreads();
        ((float4*)ws)[tid] = ((const float4*)(W1 + kc * 512))[tid];
#pragma unroll
        for (int v = 0; v < 8; ++v) {
            int j = v * 128 + tid;
            int nl = j >> 3;
            int kq = j & 7;
            int node = nodeBase + nl;
            if (node >= NN) node = NN - 1;
            float4 xv = *(const float4*)(x + (size_t)node * FIN + kc * 32 + kq * 4);
            int pcol = (((nl >> 2) ^ kq) << 2) + (nl & 3);
            float* base = (float*)&xs4[0][0] + (kq * 4) * 132 + pcol;
            base[0]   = xv.x;
            base[132] = xv.y;
            base[264] = xv.z;
            base[396] = xv.w;
        }
        __syncthreads();
#pragma unroll
        for (int k = 0; k < 32; ++k) {
            float2 wv = *(const float2*)&ws[k * 16 + fg * 2];
            int p  = k >> 2;
            int u0 = (2 * ng) ^ p;
            float4 a0 = xs4[k][u0];
            float4 a1 = xs4[k][u0 ^ 1];
            acc[0][0] += a0.x * wv.x; acc[0][1] += a0.x * wv.y;
            acc[1][0] += a0.y * wv.x; acc[1][1] += a0.y * wv.y;
            acc[2][0] += a0.z * wv.x; acc[2][1] += a0.z * wv.y;
            acc[3][0] += a0.w * wv.x; acc[3][1] += a0.w * wv.y;
            acc[4][0] += a1.x * wv.x; acc[4][1] += a1.x * wv.y;
            acc[5][0] += a1.y * wv.x; acc[5][1] += a1.y * wv.y;
            acc[6][0] += a1.z * wv.x; acc[6][1] += a1.z * wv.y;
            acc[7][0] += a1.w * wv.x; acc[7][1] += a1.w * wv.y;
        }
    }
    float* h1 = (float*)g_h1;
#pragma unroll
    for (int i = 0; i < 8; ++i) {
        int node = nodeBase + ng * 8 + i;
        if (node < NN) {
            h1[node * 16 + fg * 2 + 0] = acc[i][0];
            h1[node * 16 + fg * 2 + 1] = acc[i][1];
        }
    }
}

// ---------------- gather-reduce propagation (warp per node, no atomics) -------
// lane = eslot*4 + q : 8 edge slots x 4 float4-quarters.
__global__ void __launch_bounds__(256) gather1_kernel() {
    int warp = (blockIdx.x * 256 + threadIdx.x) >> 5;
    if (warp >= NN) return;
    int lane = threadIdx.x & 31;
    int q = lane & 3;
    int es = lane >> 2;
    int b0 = g_base[warp];
    int b1e = g_base[warp + 1];
    float4 acc = make_float4(0.f, 0.f, 0.f, 0.f);
    for (int i = b0 + es; i < b1e; i += 8) {
        int2 ew = g_edge[i];
        float nw = __int_as_float(ew.y);
        float4 v = g_h1[ew.x * 4 + q];
        acc.x += nw * v.x; acc.y += nw * v.y;
        acc.z += nw * v.z; acc.w += nw * v.w;
    }
#pragma unroll
    for (int m = 16; m >= 4; m >>= 1) {
        acc.x += __shfl_xor_sync(0xffffffffu, acc.x, m);
        acc.y += __shfl_xor_sync(0xffffffffu, acc.y, m);
        acc.z += __shfl_xor_sync(0xffffffffu, acc.z, m);
        acc.w += __shfl_xor_sync(0xffffffffu, acc.w, m);
    }
    if (es == 0) g_agg1[warp * 4 + q] = acc;
}

// layer 2: gather relu(agg1[src] + b1) * norm
__global__ void __launch_bounds__(256) gather2_kernel(const float* __restrict__ b1) {
    int warp = (blockIdx.x * 256 + threadIdx.x) >> 5;
    if (warp >= NN) return;
    int lane = threadIdx.x & 31;
    int q = lane & 3;
    int es = lane >> 2;
    float4 b = ((const float4*)b1)[q];
    int b0 = g_base[warp];
    int b1e = g_base[warp + 1];
    float4 acc = make_float4(0.f, 0.f, 0.f, 0.f);
    for (int i = b0 + es; i < b1e; i += 8) {
        int2 ew = g_edge[i];
        float nw = __int_as_float(ew.y);
        float4 v = g_agg1[ew.x * 4 + q];
        acc.x += nw * fmaxf(v.x + b.x, 0.f);
        acc.y += nw * fmaxf(v.y + b.y, 0.f);
        acc.z += nw * fmaxf(v.z + b.z, 0.f);
        acc.w += nw * fmaxf(v.w + b.w, 0.f);
    }
#pragma unroll
    for (int m = 16; m >= 4; m >>= 1) {
        acc.x += __shfl_xor_sync(0xffffffffu, acc.x, m);
        acc.y += __shfl_xor_sync(0xffffffffu, acc.y, m);
        acc.z += __shfl_xor_sync(0xffffffffu, acc.z, m);
        acc.w += __shfl_xor_sync(0xffffffffu, acc.w, m);
    }
    if (es == 0) g_agg2[warp * 4 + q] = acc;
}

// ---------------- epilogue: out = log_softmax(agg2 @ W2 + b2) -----------------
__global__ void __launch_bounds__(256) out_kernel(const float* __restrict__ W2,
                                                  const float* __restrict__ b2,
                                                  float* __restrict__ out) {
    __shared__ float w2s[HID * CC];
    __shared__ float b2s[CC];
    int tid = threadIdx.x;
    for (int i = tid; i < HID * CC; i += 256) w2s[i] = W2[i];
    if (tid < CC) b2s[tid] = b2[tid];
    __syncthreads();

    int n = blockIdx.x * blockDim.x + tid;
    if (n >= NN) return;

    float a[16];
    float4* ap = (float4*)a;
    ap[0] = g_agg2[n * 4 + 0];
    ap[1] = g_agg2[n * 4 + 1];
    ap[2] = g_agg2[n * 4 + 2];
    ap[3] = g_agg2[n * 4 + 3];

    float logit[CC];
    float mx = -1e30f;
#pragma unroll
    for (int j = 0; j < CC; ++j) {
        float s = b2s[j];
#pragma unroll
        for (int i = 0; i < 16; ++i) s += a[i] * w2s[i * CC + j];
        logit[j] = s;
        mx = fmaxf(mx, s);
    }
    float sum = 0.f;
#pragma unroll
    for (int j = 0; j < CC; ++j) sum += expf(logit[j] - mx);
    float lse = mx + logf(sum);
#pragma unroll
    for (int j = 0; j < CC; ++j) out[(size_t)n * CC + j] = logit[j] - lse;
}

// ---------------- launch ------------------------------------------------------
extern "C" void kernel_launch(void* const* d_in, const int* in_sizes, int n_in,
                              void* d_out, int out_size) {
    const float* x  = (const float*)d_in[0];
    const int*   ei = (const int*)d_in[1];
    const float* w  = (const float*)d_in[2];
    const float* W1 = (const float*)d_in[3];
    const float* b1 = (const float*)d_in[4];
    const float* W2 = (const float*)d_in[5];
    const float* b2 = (const float*)d_in[6];
    float*       out = (float*)d_out;

    zero_kernel<<<(NN + 255) / 256, 256>>>();
    deg_kernel<<<(EE + 255) / 256, 256>>>(ei, w);
    dis_kernel<<<(NN + 255) / 256, 256>>>();
    scanA_kernel<<<NB, 256>>>();
    scanB_kernel<<<1, 512>>>();
    scanC_kernel<<<(NN + 255) / 256, 256>>>();
    scatter_kernel<<<(EE + 255) / 256, 256>>>(ei, w);
    gemm1_kernel<<<(NN + 127) / 128, 128>>>(x, W1);
    gather1_kernel<<<(NN * 32 + 255) / 256, 256>>>();
    gather2_kernel<<<(NN * 32 + 255) / 256, 256>>>(b1);
    out_kernel<<<(NN + 255) / 256, 256>>>(W2, b2, out);
}

// round 7
// speedup vs baseline: 1.3498x; 1.0131x over previous
#include <cuda_runtime.h>

#define NN 100000
#define EE 3200000
#define FIN 512
#define HID 16
#define CC 40
#define NB 391          // ceil(NN/256) scan blocks

// ---------------- scratch (static device globals) -----------------------------
__device__ float  g_dis[NN];
__device__ int    g_cnt[NN];
__device__ int    g_base[NN];      // exclusive scan; mutated to row-ends by scatter
__device__ int    g_bsum[NB];
__device__ int    g_bsumx[NB];
__device__ int2   g_edge[EE];      // dest-sorted (src, weight-as-int)
__device__ float4 g_h1[NN * 4];    // h1 = x@W1, [N,16] as [N,4] float4
__device__ float4 g_agg1[NN * 4];  // layer-1 aggregation
__device__ float4 g_agg2[NN * 4];  // layer-2 aggregation (16-dim, pre-W2)

#define FMA2(d, a, b) asm("fma.rn.f32x2 %0, %1, %2, %0;" : "+l"(d) : "l"(a), "l"(b))

// ---------------- zero init ---------------------------------------------------
__global__ void zero_kernel() {
    int i = blockIdx.x * blockDim.x + threadIdx.x;
    if (i < NN) g_cnt[i] = 0;
}

// ---------------- in-degree count ---------------------------------------------
__global__ void count_kernel(const int* __restrict__ ei) {
    int e = blockIdx.x * blockDim.x + threadIdx.x;
    if (e >= EE) return;
    atomicAdd(&g_cnt[ei[EE + e]], 1);
}

// ---------------- 3-kernel exclusive scan of g_cnt -> g_base ------------------
__global__ void scanA_kernel() {
    __shared__ int s[256];
    int tid = threadIdx.x;
    int i = blockIdx.x * 256 + tid;
    int v = (i < NN) ? g_cnt[i] : 0;
    s[tid] = v;
    __syncthreads();
    for (int off = 1; off < 256; off <<= 1) {
        int t = (tid >= off) ? s[tid - off] : 0;
        __syncthreads();
        s[tid] += t;
        __syncthreads();
    }
    if (i < NN) g_base[i] = s[tid] - v;          // exclusive, intra-block
    if (tid == 255) g_bsum[blockIdx.x] = s[255];
}

__global__ void scanB_kernel() {
    __shared__ int s[512];
    int tid = threadIdx.x;
    int v = (tid < NB) ? g_bsum[tid] : 0;
    s[tid] = v;
    __syncthreads();
    for (int off = 1; off < 512; off <<= 1) {
        int t = (tid >= off) ? s[tid - off] : 0;
        __syncthreads();
        s[tid] += t;
        __syncthreads();
    }
    if (tid < NB) g_bsumx[tid] = s[tid] - v;     // exclusive block offsets
}

__global__ void scanC_kernel() {
    int i = blockIdx.x * blockDim.x + threadIdx.x;
    if (i < NN) g_base[i] += g_bsumx[i >> 8];
}

// ---------------- scatter edges (src, w); bumps g_base to row-end -------------
__global__ void scatter_kernel(const int* __restrict__ ei,
                               const float* __restrict__ w) {
    int e = blockIdx.x * blockDim.x + threadIdx.x;
    if (e >= EE) return;
    int r = ei[e];
    int c = ei[EE + e];
    int pos = atomicAdd(&g_base[c], 1);
    g_edge[pos] = make_int2(r, __float_as_int(w[e]));
}

// ---------------- weighted degree + dis via CSR gather (no atomics) -----------
__global__ void __launch_bounds__(256) degdis_kernel() {
    int node = (blockIdx.x * 256 + threadIdx.x) >> 5;
    if (node >= NN) return;
    int lane = threadIdx.x & 31;
    int b0 = node ? g_base[node - 1] : 0;   // after scatter: base[c] = row end
    int b1 = g_base[node];
    float s = 0.f;
    for (int i = b0 + lane; i < b1; i += 32) s += __int_as_float(g_edge[i].y);
#pragma unroll
    for (int m = 16; m >= 1; m >>= 1) s += __shfl_xor_sync(0xffffffffu, s, m);
    if (lane == 0) g_dis[node] = (s > 0.f) ? rsqrtf(s) : 0.f;
}

// ---------------- GEMM1: h1 = x @ W1 (f32x2 dual-rate fp32) ------------------
__global__ void __launch_bounds__(128) gemm1_kernel(const float* __restrict__ x,
                                                    const float* __restrict__ W1) {
    __shared__ float4 xs4[32][33];
    __shared__ float  ws[512];
    int tid = threadIdx.x;
    int fg = tid >> 4;               // 0..7  -> f = 2*fg, 2*fg+1
    int ng = tid & 15;               // 0..15 -> nodes ng*8 .. ng*8+7
    int nodeBase = blockIdx.x * 128;

    unsigned long long accP[4][2];   // [node-pair][f] : (node2p, node2p+1) packed
#pragma unroll
    for (int i = 0; i < 4; ++i) { accP[i][0] = 0ull; accP[i][1] = 0ull; }

    for (int kc = 0; kc < FIN / 32; ++kc) {
        __syncthreads();
        ((float4*)ws)[tid] = ((const float4*)(W1 + kc * 512))[tid];
#pragma unroll
        for (int v = 0; v < 8; ++v) {
            int j = v * 128 + tid;
            int nl = j >> 3;
            int kq = j & 7;
            int node = nodeBase + nl;
            if (node >= NN) node = NN - 1;
            float4 xv = *(const float4*)(x + (size_t)node * FIN + kc * 32 + kq * 4);
            int pcol = (((nl >> 2) ^ kq) << 2) + (nl & 3);
            float* base = (float*)&xs4[0][0] + (kq * 4) * 132 + pcol;
            base[0]   = xv.x;
            base[132] = xv.y;
            base[264] = xv.z;
            base[396] = xv.w;
        }
        __syncthreads();
#pragma unroll
        for (int k = 0; k < 32; ++k) {
            float2 wv = *(const float2*)&ws[k * 16 + fg * 2];
            unsigned long long wxx, wyy;
            asm("mov.b64 %0, {%1, %1};" : "=l"(wxx) : "f"(wv.x));
            asm("mov.b64 %0, {%1, %1};" : "=l"(wyy) : "f"(wv.y));
            int p  = k >> 2;
            int u0 = (2 * ng) ^ p;
            ulonglong2 A0 = *(const ulonglong2*)&xs4[k][u0];      // nodes 0..3
            ulonglong2 A1 = *(const ulonglong2*)&xs4[k][u0 ^ 1];  // nodes 4..7
            FMA2(accP[0][0], A0.x, wxx); FMA2(accP[0][1], A0.x, wyy);
            FMA2(accP[1][0], A0.y, wxx); FMA2(accP[1][1], A0.y, wyy);
            FMA2(accP[2][0], A1.x, wxx); FMA2(accP[2][1], A1.x, wyy);
            FMA2(accP[3][0], A1.y, wxx); FMA2(accP[3][1], A1.y, wyy);
        }
    }
    float* h1 = (float*)g_h1;
#pragma unroll
    for (int pp = 0; pp < 4; ++pp) {
        float f0a, f0b, f1a, f1b;
        asm("mov.b64 {%0, %1}, %2;" : "=f"(f0a), "=f"(f0b) : "l"(accP[pp][0]));
        asm("mov.b64 {%0, %1}, %2;" : "=f"(f1a), "=f"(f1b) : "l"(accP[pp][1]));
        int node0 = nodeBase + ng * 8 + pp * 2;
        if (node0 < NN) {
            h1[node0 * 16 + fg * 2 + 0] = f0a;
            h1[node0 * 16 + fg * 2 + 1] = f1a;
        }
        if (node0 + 1 < NN) {
            h1[(node0 + 1) * 16 + fg * 2 + 0] = f0b;
            h1[(node0 + 1) * 16 + fg * 2 + 1] = f1b;
        }
    }
}

// ---------------- gather-reduce propagation (warp per node, no atomics) -------
// lane = eslot*4 + q : 8 edge slots x 4 float4-quarters. norm on the fly.
__global__ void __launch_bounds__(256) gather1_kernel() {
    int node = (blockIdx.x * 256 + threadIdx.x) >> 5;
    if (node >= NN) return;
    int lane = threadIdx.x & 31;
    int q = lane & 3;
    int es = lane >> 2;
    float dc = g_dis[node];
    int b0 = node ? g_base[node - 1] : 0;
    int b1e = g_base[node];
    float4 acc = make_float4(0.f, 0.f, 0.f, 0.f);
    for (int i = b0 + es; i < b1e; i += 8) {
        int2 ew = g_edge[i];
        float nw = g_dis[ew.x] * __int_as_float(ew.y) * dc;
        float4 v = g_h1[ew.x * 4 + q];
        acc.x += nw * v.x; acc.y += nw * v.y;
        acc.z += nw * v.z; acc.w += nw * v.w;
    }
#pragma unroll
    for (int m = 16; m >= 4; m >>= 1) {
        acc.x += __shfl_xor_sync(0xffffffffu, acc.x, m);
        acc.y += __shfl_xor_sync(0xffffffffu, acc.y, m);
        acc.z += __shfl_xor_sync(0xffffffffu, acc.z, m);
        acc.w += __shfl_xor_sync(0xffffffffu, acc.w, m);
    }
    if (es == 0) g_agg1[node * 4 + q] = acc;
}

// layer 2: gather relu(agg1[src] + b1) * norm
__global__ void __launch_bounds__(256) gather2_kernel(const float* __restrict__ b1) {
    int node = (blockIdx.x * 256 + threadIdx.x) >> 5;
    if (node >= NN) return;
    int lane = threadIdx.x & 31;
    int q = lane & 3;
    int es = lane >> 2;
    float4 b = ((const float4*)b1)[q];
    float dc = g_dis[node];
    int b0 = node ? g_base[node - 1] : 0;
    int b1e = g_base[node];
    float4 acc = make_float4(0.f, 0.f, 0.f, 0.f);
    for (int i = b0 + es; i < b1e; i += 8) {
        int2 ew = g_edge[i];
        float nw = g_dis[ew.x] * __int_as_float(ew.y) * dc;
        float4 v = g_agg1[ew.x * 4 + q];
        acc.x += nw * fmaxf(v.x + b.x, 0.f);
        acc.y += nw * fmaxf(v.y + b.y, 0.f);
        acc.z += nw * fmaxf(v.z + b.z, 0.f);
        acc.w += nw * fmaxf(v.w + b.w, 0.f);
    }
#pragma unroll
    for (int m = 16; m >= 4; m >>= 1) {
        acc.x += __shfl_xor_sync(0xffffffffu, acc.x, m);
        acc.y += __shfl_xor_sync(0xffffffffu, acc.y, m);
        acc.z += __shfl_xor_sync(0xffffffffu, acc.z, m);
        acc.w += __shfl_xor_sync(0xffffffffu, acc.w, m);
    }
    if (es == 0) g_agg2[node * 4 + q] = acc;
}

// ---------------- epilogue: out = log_softmax(agg2 @ W2 + b2) -----------------
__global__ void __launch_bounds__(256) out_kernel(const float* __restrict__ W2,
                                                  const float* __restrict__ b2,
                                                  float* __restrict__ out) {
    __shared__ float w2s[HID * CC];
    __shared__ float b2s[CC];
    int tid = threadIdx.x;
    for (int i = tid; i < HID * CC; i += 256) w2s[i] = W2[i];
    if (tid < CC) b2s[tid] = b2[tid];
    __syncthreads();

    int n = blockIdx.x * blockDim.x + tid;
    if (n >= NN) return;

    float a[16];
    float4* ap = (float4*)a;
    ap[0] = g_agg2[n * 4 + 0];
    ap[1] = g_agg2[n * 4 + 1];
    ap[2] = g_agg2[n * 4 + 2];
    ap[3] = g_agg2[n * 4 + 3];

    float logit[CC];
    float mx = -1e30f;
#pragma unroll
    for (int j = 0; j < CC; ++j) {
        float s = b2s[j];
#pragma unroll
        for (int i = 0; i < 16; ++i) s += a[i] * w2s[i * CC + j];
        logit[j] = s;
        mx = fmaxf(mx, s);
    }
    float sum = 0.f;
#pragma unroll
    for (int j = 0; j < CC; ++j) sum += expf(logit[j] - mx);
    float lse = mx + logf(sum);
#pragma unroll
    for (int j = 0; j < CC; ++j) out[(size_t)n * CC + j] = logit[j] - lse;
}

// ---------------- launch ------------------------------------------------------
extern "C" void kernel_launch(void* const* d_in, const int* in_sizes, int n_in,
                              void* d_out, int out_size) {
    const float* x  = (const float*)d_in[0];
    const int*   ei = (const int*)d_in[1];
    const float* w  = (const float*)d_in[2];
    const float* W1 = (const float*)d_in[3];
    const float* b1 = (const float*)d_in[4];
    const float* W2 = (const float*)d_in[5];
    const float* b2 = (const float*)d_in[6];
    float*       out = (float*)d_out;

    zero_kernel<<<(NN + 255) / 256, 256>>>();
    count_kernel<<<(EE + 255) / 256, 256>>>(ei);
    scanA_kernel<<<NB, 256>>>();
    gemm1_kernel<<<(NN + 127) / 128, 128>>>(x, W1);   // 4th launch -> gets profiled
    scanB_kernel<<<1, 512>>>();
    scanC_kernel<<<(NN + 255) / 256, 256>>>();
    scatter_kernel<<<(EE + 255) / 256, 256>>>(ei, w);
    degdis_kernel<<<(NN * 32 + 255) / 256, 256>>>();
    gather1_kernel<<<(NN * 32 + 255) / 256, 256>>>();
    gather2_kernel<<<(NN * 32 + 255) / 256, 256>>>(b1);
    out_kernel<<<(NN + 255) / 256, 256>>>(W2, b2, out);
}

// round 8
// speedup vs baseline: 1.6562x; 1.2270x over previous
#include <cuda_runtime.h>

#define NN 100000
#define EE 3200000
#define FIN 512
#define HID 16
#define CC 40
#define NB 391          // ceil(NN/256) scan blocks

// ---------------- scratch (static device globals) -----------------------------
__device__ float  g_dis[NN];
__device__ int    g_cnt[NN];
__device__ int    g_base[NN];      // exclusive scan; mutated to row-ends by scatter
__device__ int    g_bsum[NB];
__device__ int    g_bsumx[NB];
__device__ int2   g_edge[EE];      // dest-sorted (src, weight-as-int)
__device__ float4 g_h1[NN * 4];    // h1 = x@W1, [N,16] as [N,4] float4
__device__ float4 g_agg1[NN * 4];  // layer-1 aggregation
__device__ float4 g_agg2[NN * 4];  // layer-2 aggregation (16-dim, pre-W2)

#define FMA2(d, a, b) asm("fma.rn.f32x2 %0, %1, %2, %0;" : "+l"(d) : "l"(a), "l"(b))
#define ZIP(d, a, b)  asm("mov.b64 %0, {%1, %2};" : "=l"(d) : "f"(a), "f"(b))
#define CPA16(s, g)   asm volatile("cp.async.cg.shared.global [%0], [%1], 16;" :: "r"(s), "l"(g))
#define CP_COMMIT()   asm volatile("cp.async.commit_group;")
#define CP_WAIT(n)    asm volatile("cp.async.wait_group %0;" :: "n"(n))

// ---------------- zero init ---------------------------------------------------
__global__ void zero_kernel() {
    int i = blockIdx.x * blockDim.x + threadIdx.x;
    if (i < NN) g_cnt[i] = 0;
}

// ---------------- in-degree count ---------------------------------------------
__global__ void count_kernel(const int* __restrict__ ei) {
    int e = blockIdx.x * blockDim.x + threadIdx.x;
    if (e >= EE) return;
    atomicAdd(&g_cnt[ei[EE + e]], 1);
}

// ---------------- 3-kernel exclusive scan of g_cnt -> g_base ------------------
__global__ void scanA_kernel() {
    __shared__ int s[256];
    int tid = threadIdx.x;
    int i = blockIdx.x * 256 + tid;
    int v = (i < NN) ? g_cnt[i] : 0;
    s[tid] = v;
    __syncthreads();
    for (int off = 1; off < 256; off <<= 1) {
        int t = (tid >= off) ? s[tid - off] : 0;
        __syncthreads();
        s[tid] += t;
        __syncthreads();
    }
    if (i < NN) g_base[i] = s[tid] - v;          // exclusive, intra-block
    if (tid == 255) g_bsum[blockIdx.x] = s[255];
}

__global__ void scanB_kernel() {
    __shared__ int s[512];
    int tid = threadIdx.x;
    int v = (tid < NB) ? g_bsum[tid] : 0;
    s[tid] = v;
    __syncthreads();
    for (int off = 1; off < 512; off <<= 1) {
        int t = (tid >= off) ? s[tid - off] : 0;
        __syncthreads();
        s[tid] += t;
        __syncthreads();
    }
    if (tid < NB) g_bsumx[tid] = s[tid] - v;     // exclusive block offsets
}

__global__ void scanC_kernel() {
    int i = blockIdx.x * blockDim.x + threadIdx.x;
    if (i < NN) g_base[i] += g_bsumx[i >> 8];
}

// ---------------- scatter edges (src, w); bumps g_base to row-end -------------
__global__ void scatter_kernel(const int* __restrict__ ei,
                               const float* __restrict__ w) {
    int e = blockIdx.x * blockDim.x + threadIdx.x;
    if (e >= EE) return;
    int r = ei[e];
    int c = ei[EE + e];
    int pos = atomicAdd(&g_base[c], 1);
    g_edge[pos] = make_int2(r, __float_as_int(w[e]));
}

// ---------------- weighted degree + dis via CSR gather (no atomics) -----------
__global__ void __launch_bounds__(256) degdis_kernel() {
    int node = (blockIdx.x * 256 + threadIdx.x) >> 5;
    if (node >= NN) return;
    int lane = threadIdx.x & 31;
    int b0 = node ? g_base[node - 1] : 0;   // after scatter: base[c] = row end
    int b1 = g_base[node];
    float s = 0.f;
    for (int i = b0 + lane; i < b1; i += 32) s += __int_as_float(g_edge[i].y);
#pragma unroll
    for (int m = 16; m >= 1; m >>= 1) s += __shfl_xor_sync(0xffffffffu, s, m);
    if (lane == 0) g_dis[node] = (s > 0.f) ? rsqrtf(s) : 0.f;
}

// ---------------- GEMM1 v3: h1 = x @ W1 ---------------------------------------
// 64 threads/block: 16 ng x 4 fg. Tile 128 nodes x 16 f. Thread: 8 nodes x 4 f.
// Row-major x smem (pitch 5 float4/node), same-warp fg lanes broadcast x reads.
// k-chunk 16, cp.async double-buffered. f32x2 FMAs pack adjacent k; accumulator
// halves hold k-split partial sums, folded at the end.
#define KCH 16
#define NCHUNK (FIN / KCH)   // 32
__global__ void __launch_bounds__(64) gemm1_kernel(const float* __restrict__ x,
                                                   const float* __restrict__ W1) {
    __shared__ float4 xs[2][128 * 5];   // [buf][node*5 + kq], kq 0..3, pad f4
    __shared__ float4 wsb[2][64];       // [buf][k*4 + f4col]  (16 k x 16 f)
    int tid = threadIdx.x;
    int ng = tid & 15;
    int fg = tid >> 4;                   // 0..3 -> f = fg*4 .. fg*4+3
    int nodeBase = blockIdx.x * 128;

    // per-thread gmem coords for the cp.async loads
    int xnl = tid >> 2;                  // node-local for x loads (plus 16*s)
    int xkq = tid & 3;
    int wk  = tid >> 2;                  // k row for w load
    int wf4 = tid & 3;

    unsigned long long acc[8][4];
#pragma unroll
    for (int i = 0; i < 8; ++i)
#pragma unroll
        for (int f = 0; f < 4; ++f) acc[i][f] = 0ull;

    // ---- prologue: prefetch chunk 0 into buf 0
    {
#pragma unroll
        for (int s = 0; s < 8; ++s) {
            int nl = xnl + 16 * s;
            int node = nodeBase + nl; if (node >= NN) node = NN - 1;
            unsigned dst = (unsigned)__cvta_generic_to_shared(&xs[0][nl * 5 + xkq]);
            CPA16(dst, x + (size_t)node * FIN + xkq * 4);
        }
        unsigned dw = (unsigned)__cvta_generic_to_shared(&wsb[0][tid]);
        CPA16(dw, W1 + (size_t)wk * 16 + wf4 * 4);
        CP_COMMIT();
    }

    for (int kc = 0; kc < NCHUNK; ++kc) {
        int cur = kc & 1;
        if (kc + 1 < NCHUNK) {
            int kb = (kc + 1) * KCH;
#pragma unroll
            for (int s = 0; s < 8; ++s) {
                int nl = xnl + 16 * s;
                int node = nodeBase + nl; if (node >= NN) node = NN - 1;
                unsigned dst = (unsigned)__cvta_generic_to_shared(&xs[cur ^ 1][nl * 5 + xkq]);
                CPA16(dst, x + (size_t)node * FIN + kb + xkq * 4);
            }
            unsigned dw = (unsigned)__cvta_generic_to_shared(&wsb[cur ^ 1][tid]);
            CPA16(dw, W1 + (size_t)(kb + wk) * 16 + wf4 * 4);
            CP_COMMIT();
            CP_WAIT(1);
        } else {
            CP_WAIT(0);
        }
        __syncthreads();

#pragma unroll
        for (int kq = 0; kq < 4; ++kq) {
            float4 w0 = wsb[cur][(4 * kq + 0) * 4 + fg];
            float4 w1 = wsb[cur][(4 * kq + 1) * 4 + fg];
            float4 w2 = wsb[cur][(4 * kq + 2) * 4 + fg];
            float4 w3 = wsb[cur][(4 * kq + 3) * 4 + fg];
            unsigned long long pA0, pA1, pA2, pA3, pB0, pB1, pB2, pB3;
            ZIP(pA0, w0.x, w1.x); ZIP(pA1, w0.y, w1.y);
            ZIP(pA2, w0.z, w1.z); ZIP(pA3, w0.w, w1.w);
            ZIP(pB0, w2.x, w3.x); ZIP(pB1, w2.y, w3.y);
            ZIP(pB2, w2.z, w3.z); ZIP(pB3, w2.w, w3.w);
#pragma unroll
            for (int i = 0; i < 8; ++i) {
                ulonglong2 xu = *(const ulonglong2*)&xs[cur][(ng + 16 * i) * 5 + kq];
                FMA2(acc[i][0], xu.x, pA0); FMA2(acc[i][1], xu.x, pA1);
                FMA2(acc[i][2], xu.x, pA2); FMA2(acc[i][3], xu.x, pA3);
                FMA2(acc[i][0], xu.y, pB0); FMA2(acc[i][1], xu.y, pB1);
                FMA2(acc[i][2], xu.y, pB2); FMA2(acc[i][3], xu.y, pB3);
            }
        }
        __syncthreads();
    }

    // ---- fold k-split halves and store (one float4 per node)
#pragma unroll
    for (int i = 0; i < 8; ++i) {
        int node = nodeBase + ng + 16 * i;
        if (node >= NN) continue;
        float4 o;
        float lo, hi;
        asm("mov.b64 {%0, %1}, %2;" : "=f"(lo), "=f"(hi) : "l"(acc[i][0])); o.x = lo + hi;
        asm("mov.b64 {%0, %1}, %2;" : "=f"(lo), "=f"(hi) : "l"(acc[i][1])); o.y = lo + hi;
        asm("mov.b64 {%0, %1}, %2;" : "=f"(lo), "=f"(hi) : "l"(acc[i][2])); o.z = lo + hi;
        asm("mov.b64 {%0, %1}, %2;" : "=f"(lo), "=f"(hi) : "l"(acc[i][3])); o.w = lo + hi;
        g_h1[node * 4 + fg] = o;
    }
}

// ---------------- gather-reduce propagation (warp per node, no atomics) -------
// lane = eslot*4 + q : 8 edge slots x 4 float4-quarters. norm on the fly.
__global__ void __launch_bounds__(256) gather1_kernel() {
    int node = (blockIdx.x * 256 + threadIdx.x) >> 5;
    if (node >= NN) return;
    int lane = threadIdx.x & 31;
    int q = lane & 3;
    int es = lane >> 2;
    float dc = g_dis[node];
    int b0 = node ? g_base[node - 1] : 0;
    int b1e = g_base[node];
    float4 acc = make_float4(0.f, 0.f, 0.f, 0.f);
    for (int i = b0 + es; i < b1e; i += 8) {
        int2 ew = g_edge[i];
        float nw = g_dis[ew.x] * __int_as_float(ew.y) * dc;
        float4 v = g_h1[ew.x * 4 + q];
        acc.x += nw * v.x; acc.y += nw * v.y;
        acc.z += nw * v.z; acc.w += nw * v.w;
    }
#pragma unroll
    for (int m = 16; m >= 4; m >>= 1) {
        acc.x += __shfl_xor_sync(0xffffffffu, acc.x, m);
        acc.y += __shfl_xor_sync(0xffffffffu, acc.y, m);
        acc.z += __shfl_xor_sync(0xffffffffu, acc.z, m);
        acc.w += __shfl_xor_sync(0xffffffffu, acc.w, m);
    }
    if (es == 0) g_agg1[node * 4 + q] = acc;
}

// layer 2: gather relu(agg1[src] + b1) * norm
__global__ void __launch_bounds__(256) gather2_kernel(const float* __restrict__ b1) {
    int node = (blockIdx.x * 256 + threadIdx.x) >> 5;
    if (node >= NN) return;
    int lane = threadIdx.x & 31;
    int q = lane & 3;
    int es = lane >> 2;
    float4 b = ((const float4*)b1)[q];
    float dc = g_dis[node];
    int b0 = node ? g_base[node - 1] : 0;
    int b1e = g_base[node];
    float4 acc = make_float4(0.f, 0.f, 0.f, 0.f);
    for (int i = b0 + es; i < b1e; i += 8) {
        int2 ew = g_edge[i];
        float nw = g_dis[ew.x] * __int_as_float(ew.y) * dc;
        float4 v = g_agg1[ew.x * 4 + q];
        acc.x += nw * fmaxf(v.x + b.x, 0.f);
        acc.y += nw * fmaxf(v.y + b.y, 0.f);
        acc.z += nw * fmaxf(v.z + b.z, 0.f);
        acc.w += nw * fmaxf(v.w + b.w, 0.f);
    }
#pragma unroll
    for (int m = 16; m >= 4; m >>= 1) {
        acc.x += __shfl_xor_sync(0xffffffffu, acc.x, m);
        acc.y += __shfl_xor_sync(0xffffffffu, acc.y, m);
        acc.z += __shfl_xor_sync(0xffffffffu, acc.z, m);
        acc.w += __shfl_xor_sync(0xffffffffu, acc.w, m);
    }
    if (es == 0) g_agg2[node * 4 + q] = acc;
}

// ---------------- epilogue: out = log_softmax(agg2 @ W2 + b2) -----------------
__global__ void __launch_bounds__(256) out_kernel(const float* __restrict__ W2,
                                                  const float* __restrict__ b2,
                                                  float* __restrict__ out) {
    __shared__ float w2s[HID * CC];
    __shared__ float b2s[CC];
    int tid = threadIdx.x;
    for (int i = tid; i < HID * CC; i += 256) w2s[i] = W2[i];
    if (tid < CC) b2s[tid] = b2[tid];
    __syncthreads();

    int n = blockIdx.x * blockDim.x + tid;
    if (n >= NN) return;

    float a[16];
    float4* ap = (float4*)a;
    ap[0] = g_agg2[n * 4 + 0];
    ap[1] = g_agg2[n * 4 + 1];
    ap[2] = g_agg2[n * 4 + 2];
    ap[3] = g_agg2[n * 4 + 3];

    float logit[CC];
    float mx = -1e30f;
#pragma unroll
    for (int j = 0; j < CC; ++j) {
        float s = b2s[j];
#pragma unroll
        for (int i = 0; i < 16; ++i) s += a[i] * w2s[i * CC + j];
        logit[j] = s;
        mx = fmaxf(mx, s);
    }
    float sum = 0.f;
#pragma unroll
    for (int j = 0; j < CC; ++j) sum += expf(logit[j] - mx);
    float lse = mx + logf(sum);
#pragma unroll
    for (int j = 0; j < CC; ++j) out[(size_t)n * CC + j] = logit[j] - lse;
}

// ---------------- launch ------------------------------------------------------
extern "C" void kernel_launch(void* const* d_in, const int* in_sizes, int n_in,
                              void* d_out, int out_size) {
    const float* x  = (const float*)d_in[0];
    const int*   ei = (const int*)d_in[1];
    const float* w  = (const float*)d_in[2];
    const float* W1 = (const float*)d_in[3];
    const float* b1 = (const float*)d_in[4];
    const float* W2 = (const float*)d_in[5];
    const float* b2 = (const float*)d_in[6];
    float*       out = (float*)d_out;

    zero_kernel<<<(NN + 255) / 256, 256>>>();
    count_kernel<<<(EE + 255) / 256, 256>>>(ei);
    scanA_kernel<<<NB, 256>>>();
    gemm1_kernel<<<(NN + 127) / 128, 64>>>(x, W1);   // 4th launch -> gets profiled
    scanB_kernel<<<1, 512>>>();
    scanC_kernel<<<(NN + 255) / 256, 256>>>();
    scatter_kernel<<<(EE + 255) / 256, 256>>>(ei, w);
    degdis_kernel<<<(NN * 32 + 255) / 256, 256>>>();
    gather1_kernel<<<(NN * 32 + 255) / 256, 256>>>();
    gather2_kernel<<<(NN * 32 + 255) / 256, 256>>>(b1);
    out_kernel<<<(NN + 255) / 256, 256>>>(W2, b2, out);
}